// round 16
// baseline (speedup 1.0000x reference)
#include <cuda_runtime.h>
#include <cuda_bf16.h>
#include <float.h>
#include <cstdint>

#define NROWS 16384
#define DIM   2048
#define DSTR  2049
#define KC    1000
#define NPAD  1024
#define NSTEPS 64            // 2048/32 ; all 3 segments fused per k-step
#define A_TILE 5120          // 64 rows x 80B
#define B_TILE 10240         // 128 rows x 80B
#define STAGE_BYTES 30720    // ah, al, bh, bl
#define NSTAGE 3
#define SM_TOTAL (NSTAGE * STAGE_BYTES)   // 92160

// ---------------- scratch ----------------
__device__ unsigned long long g_best[NROWS];
__device__ float g_inv[NROWS];
__device__ float g_halfc[NPAD];
__device__ float g_clast[NPAD];
__device__ __nv_bfloat16 g_ahi[(size_t)NROWS * DIM];
__device__ __nv_bfloat16 g_alo[(size_t)NROWS * DIM];
__device__ __nv_bfloat16 g_chi[(size_t)NPAD * DIM];
__device__ __nv_bfloat16 g_clo[(size_t)NPAD * DIM];

__device__ __forceinline__ uint32_t smem_u32(const void* p) {
    uint32_t a;
    asm("{ .reg .u64 t; cvta.to.shared.u64 t, %1; cvt.u32.u64 %0, t; }" : "=r"(a) : "l"(p));
    return a;
}
__device__ __forceinline__ void cp16(uint32_t saddr, const void* gptr) {
    asm volatile("cp.async.cg.shared.global [%0], [%1], 16;"
                 :: "r"(saddr), "l"(__cvta_generic_to_global(gptr)));
}
#define CP_COMMIT() asm volatile("cp.async.commit_group;" ::: "memory")
#define CP_WAIT(n)  asm volatile("cp.async.wait_group %0;" :: "n"(n) : "memory")

__device__ __forceinline__ void ldmx4(uint32_t* r, uint32_t addr) {
    asm volatile("ldmatrix.sync.aligned.m8n8.x4.shared.b16 {%0,%1,%2,%3}, [%4];"
                 : "=r"(r[0]), "=r"(r[1]), "=r"(r[2]), "=r"(r[3]) : "r"(addr));
}
__device__ __forceinline__ void mma16816(float* d, const uint32_t* a, const uint32_t* b) {
    asm volatile(
        "mma.sync.aligned.m16n8k16.row.col.f32.bf16.bf16.f32 "
        "{%0,%1,%2,%3}, {%4,%5,%6,%7}, {%8,%9}, {%0,%1,%2,%3};"
        : "+f"(d[0]), "+f"(d[1]), "+f"(d[2]), "+f"(d[3])
        : "r"(a[0]), "r"(a[1]), "r"(a[2]), "r"(a[3]), "r"(b[0]), "r"(b[1]));
}

// ---------------- prep ----------------
__global__ void k_init_best() {
    int i = blockIdx.x * blockDim.x + threadIdx.x;
    if (i < NROWS) g_best[i] = 0ull;
}

__global__ __launch_bounds__(256) void k_convert_rowinv(const float* __restrict__ A) {
    const int row = blockIdx.x;
    const int tid = threadIdx.x;
    const float4* p = (const float4*)(A + (size_t)row * DIM);
    float sum = 0.f;
    #pragma unroll
    for (int i = 0; i < 2; ++i) {
        int idx = tid + i * 256;
        float4 v = p[idx];
        float f[4] = {v.x, v.y, v.z, v.w};
        sum = fmaf(v.x, v.x, sum); sum = fmaf(v.y, v.y, sum);
        sum = fmaf(v.z, v.z, sum); sum = fmaf(v.w, v.w, sum);
        __nv_bfloat16 h[4], l[4];
        #pragma unroll
        for (int j = 0; j < 4; j++) {
            h[j] = __float2bfloat16(f[j]);
            l[j] = __float2bfloat16(f[j] - __bfloat162float(h[j]));
        }
        size_t o = (size_t)row * 512 + idx;
        ((ushort4*)g_ahi)[o] = make_ushort4(__bfloat16_as_ushort(h[0]), __bfloat16_as_ushort(h[1]),
                                            __bfloat16_as_ushort(h[2]), __bfloat16_as_ushort(h[3]));
        ((ushort4*)g_alo)[o] = make_ushort4(__bfloat16_as_ushort(l[0]), __bfloat16_as_ushort(l[1]),
                                            __bfloat16_as_ushort(l[2]), __bfloat16_as_ushort(l[3]));
    }
    __shared__ float red[8];
    #pragma unroll
    for (int o = 16; o > 0; o >>= 1) sum += __shfl_xor_sync(0xffffffffu, sum, o);
    if ((tid & 31) == 0) red[tid >> 5] = sum;
    __syncthreads();
    if (tid == 0) {
        float s = 0.f;
        #pragma unroll
        for (int w = 0; w < 8; w++) s += red[w];
        g_inv[row] = (float)(1.0 / sqrt((double)s + 1.0));
    }
}

__global__ void k_prep_centers(const float* __restrict__ C) {
    int k = blockIdx.x;
    int tid = threadIdx.x;
    if (k >= KC) {
        for (int i = tid; i < DIM; i += 256) {
            g_chi[(size_t)k * DIM + i] = __float2bfloat16(0.f);
            g_clo[(size_t)k * DIM + i] = __float2bfloat16(0.f);
        }
        if (tid == 0) { g_halfc[k] = 1e30f; g_clast[k] = 0.f; }
        return;
    }
    const float* row = C + (size_t)k * DSTR;
    double sum = 0.0;
    for (int i = tid; i < DSTR; i += 256) {
        float v = row[i];
        sum += (double)v * (double)v;
        if (i < DIM) {
            __nv_bfloat16 h = __float2bfloat16(v);
            g_chi[(size_t)k * DIM + i] = h;
            g_clo[(size_t)k * DIM + i] = __float2bfloat16(v - __bfloat162float(h));
        }
    }
    __shared__ double red[8];
    #pragma unroll
    for (int o = 16; o > 0; o >>= 1) sum += __shfl_xor_sync(0xffffffffu, sum, o);
    if ((tid & 31) == 0) red[tid >> 5] = sum;
    __syncthreads();
    if (tid == 0) {
        double s = 0.0;
        #pragma unroll
        for (int w = 0; w < 8; w++) s += red[w];
        g_halfc[k] = (float)(0.5 * s);
        g_clast[k] = row[DIM];
    }
}

// ---------------- HMMA bf16-split GEMM + fused argmax ----------------
// CTA tile 64(m) x 128(n): 2048 CTAs -> 6.92 waves on 296 slots (98.8% eff).
// 128 threads, 4 warps 2x2, warp tile 32x64, fused 3-product per k-step.
__global__ __launch_bounds__(128) void k_gemm_mma() {
    extern __shared__ char smem[];
    const uint32_t sb = smem_u32(smem);
    const int tid = threadIdx.x;
    const int wid = tid >> 5, lane = tid & 31;
    const int gid = lane >> 2, tig = lane & 3;
    const int n0 = blockIdx.x * 128;
    const int m0 = blockIdx.y * 64;
    const int wm = wid >> 1;       // 0..1, 32 m-rows
    const int wn = wid & 1;        // 0..1, 64 n-cols

    float acc[2][8][4];
    #pragma unroll
    for (int a = 0; a < 2; a++)
        #pragma unroll
        for (int b = 0; b < 8; b++)
            #pragma unroll
            for (int c = 0; c < 4; c++) acc[a][b][c] = 0.f;

    const int rc = tid >> 2;              // 0..31
    const int cc = tid & 3;               // 16B chunk in 64B row slab

    const uint32_t aoff = (uint32_t)((wm * 32 + (lane & 15)) * 80 + (lane >> 4) * 16);
    const uint32_t boff = (uint32_t)((wn * 64 + (lane & 7) + ((lane >> 4) << 3)) * 80
                                     + ((lane >> 3) & 1) * 16);

    // stage layout: [ah(5120) | al(5120) | bh(10240) | bl(10240)]
    #define LOAD_STAGE(s, st) do {                                              \
        int k0_ = (s) << 5;                                                     \
        uint32_t sa_ = sb + (st) * STAGE_BYTES;                                 \
        _Pragma("unroll")                                                       \
        for (int rb_ = 0; rb_ < 2; rb_++) {                                     \
            int r_ = rc + rb_ * 32;                                             \
            size_t ao_ = (size_t)(m0 + r_) * DIM + k0_ + cc * 8;                \
            uint32_t so_ = r_ * 80 + cc * 16;                                   \
            cp16(sa_ + 0 * A_TILE + so_, g_ahi + ao_);                          \
            cp16(sa_ + 1 * A_TILE + so_, g_alo + ao_);                          \
        }                                                                       \
        _Pragma("unroll")                                                       \
        for (int rb_ = 0; rb_ < 4; rb_++) {                                     \
            int r_ = rc + rb_ * 32;                                             \
            size_t bo_ = (size_t)(n0 + r_) * DIM + k0_ + cc * 8;                \
            uint32_t so_ = r_ * 80 + cc * 16;                                   \
            cp16(sa_ + 2 * A_TILE + so_, g_chi + bo_);                          \
            cp16(sa_ + 2 * A_TILE + B_TILE + so_, g_clo + bo_);                 \
        }                                                                       \
    } while (0)

    LOAD_STAGE(0, 0); CP_COMMIT();
    LOAD_STAGE(1, 1); CP_COMMIT();

    for (int s = 0; s < NSTEPS; ++s) {
        CP_WAIT(1);
        __syncthreads();
        if (s + 2 < NSTEPS) { LOAD_STAGE(s + 2, (s + 2) % NSTAGE); }
        CP_COMMIT();

        const uint32_t st = sb + (s % NSTAGE) * STAGE_BYTES;
        const uint32_t stB = st + 2 * A_TILE;
        #pragma unroll
        for (int kk = 0; kk < 2; ++kk) {
            uint32_t af_h[2][4], af_l[2][4];
            #pragma unroll
            for (int mf = 0; mf < 2; ++mf) {
                ldmx4(af_h[mf], st + 0 * A_TILE + aoff + mf * 1280 + kk * 32);
                ldmx4(af_l[mf], st + 1 * A_TILE + aoff + mf * 1280 + kk * 32);
            }
            uint32_t bf_h[8][2], bf_l[8][2];
            #pragma unroll
            for (int np = 0; np < 4; ++np) {
                uint32_t r[4];
                ldmx4(r, stB + boff + np * 1280 + kk * 32);
                bf_h[2 * np][0] = r[0]; bf_h[2 * np][1] = r[1];
                bf_h[2 * np + 1][0] = r[2]; bf_h[2 * np + 1][1] = r[3];
                ldmx4(r, stB + B_TILE + boff + np * 1280 + kk * 32);
                bf_l[2 * np][0] = r[0]; bf_l[2 * np][1] = r[1];
                bf_l[2 * np + 1][0] = r[2]; bf_l[2 * np + 1][1] = r[3];
            }
            #pragma unroll
            for (int mf = 0; mf < 2; ++mf)
                #pragma unroll
                for (int nf = 0; nf < 8; ++nf)
                    mma16816(acc[mf][nf], af_h[mf], bf_h[nf]);
            #pragma unroll
            for (int mf = 0; mf < 2; ++mf)
                #pragma unroll
                for (int nf = 0; nf < 8; ++nf)
                    mma16816(acc[mf][nf], af_h[mf], bf_l[nf]);
            #pragma unroll
            for (int mf = 0; mf < 2; ++mf)
                #pragma unroll
                for (int nf = 0; nf < 8; ++nf)
                    mma16816(acc[mf][nf], af_l[mf], bf_h[nf]);
        }
    }

    // -------- fused epilogue --------
    float cl[16], hc[16];
    #pragma unroll
    for (int nf = 0; nf < 8; ++nf)
        #pragma unroll
        for (int j = 0; j < 2; ++j) {
            int n = n0 + wn * 64 + nf * 8 + 2 * tig + j;
            cl[nf * 2 + j] = g_clast[n];
            hc[nf * 2 + j] = g_halfc[n];
        }

    #pragma unroll
    for (int mf = 0; mf < 2; ++mf)
        #pragma unroll
        for (int h = 0; h < 2; ++h) {
            int m = m0 + wm * 32 + mf * 16 + gid + 8 * h;
            float invm = g_inv[m];
            float bs = -FLT_MAX;
            int bn = 0x7FFFFFFF;
            #pragma unroll
            for (int nf = 0; nf < 8; ++nf)
                #pragma unroll
                for (int j = 0; j < 2; ++j) {
                    float s = fmaf(acc[mf][nf][2 * h + j] + cl[nf * 2 + j], invm,
                                   -hc[nf * 2 + j]);
                    int n = n0 + wn * 64 + nf * 8 + 2 * tig + j;
                    if (s > bs) { bs = s; bn = n; }
                }
            #pragma unroll
            for (int o = 1; o <= 2; o <<= 1) {
                float so = __shfl_xor_sync(0xffffffffu, bs, o);
                int   no = __shfl_xor_sync(0xffffffffu, bn, o);
                if (so > bs || (so == bs && no < bn)) { bs = so; bn = no; }
            }
            if (tig == 0) {
                unsigned sbits = __float_as_uint(bs);
                sbits = (sbits & 0x80000000u) ? ~sbits : (sbits | 0x80000000u);
                unsigned long long packed = ((unsigned long long)sbits << 32)
                    | (unsigned long long)(0xFFFFFFFFu - (unsigned)bn);
                atomicMax(&g_best[m], packed);
            }
        }
}

__global__ void k_decode(float* __restrict__ out) {
    int i = blockIdx.x * blockDim.x + threadIdx.x;
    if (i < NROWS)
        out[i] = (float)(0xFFFFFFFFu - (unsigned)(g_best[i] & 0xFFFFFFFFull));
}

extern "C" void kernel_launch(void* const* d_in, const int* in_sizes, int n_in,
                              void* d_out, int out_size) {
    (void)in_sizes; (void)n_in; (void)out_size;
    const float* feats = (const float*)d_in[0];
    const float* initc = (const float*)d_in[1];
    float* out = (float*)d_out;

    cudaFuncSetAttribute(k_gemm_mma, cudaFuncAttributeMaxDynamicSharedMemorySize, SM_TOTAL);

    k_init_best<<<(NROWS + 255) / 256, 256>>>();
    k_convert_rowinv<<<NROWS, 256>>>(feats);
    k_prep_centers<<<NPAD, 256>>>(initc);

    dim3 grid(NPAD / 128, NROWS / 64);   // (8, 256) = 2048 CTAs
    k_gemm_mma<<<grid, 128, SM_TOTAL>>>();

    k_decode<<<(NROWS + 255) / 256, 256>>>(out);
}

// round 17
// speedup vs baseline: 1.1965x; 1.1965x over previous
#include <cuda_runtime.h>
#include <cuda_fp16.h>
#include <float.h>
#include <cstdint>

#define NROWS 16384
#define DIM   2048
#define DSTR  2049
#define KC    1000
#define NPAD  1024
#define NSTEPS 64            // 2048/32 ; all 3 segments fused per k-step
#define TILE_B 10240         // one 128-row x 80B tile
#define STAGE_BYTES 40960    // ah, al, bh, bl tiles
#define NSTAGE 2
#define SM_TOTAL (NSTAGE * STAGE_BYTES)   // 81920

// ---------------- scratch ----------------
__device__ unsigned long long g_best[NROWS];
__device__ float g_inv[NROWS];
__device__ float g_halfc[NPAD];
__device__ float g_clast[NPAD];
__device__ __half g_ahi[(size_t)NROWS * DIM];
__device__ __half g_alo[(size_t)NROWS * DIM];
__device__ __half g_chi[(size_t)NPAD * DIM];
__device__ __half g_clo[(size_t)NPAD * DIM];

__device__ __forceinline__ uint32_t smem_u32(const void* p) {
    uint32_t a;
    asm("{ .reg .u64 t; cvta.to.shared.u64 t, %1; cvt.u32.u64 %0, t; }" : "=r"(a) : "l"(p));
    return a;
}
__device__ __forceinline__ void cp16(uint32_t saddr, const void* gptr) {
    asm volatile("cp.async.cg.shared.global [%0], [%1], 16;"
                 :: "r"(saddr), "l"(__cvta_generic_to_global(gptr)));
}
#define CP_COMMIT() asm volatile("cp.async.commit_group;" ::: "memory")
#define CP_WAIT(n)  asm volatile("cp.async.wait_group %0;" :: "n"(n) : "memory")

__device__ __forceinline__ void ldmx4(uint32_t* r, uint32_t addr) {
    asm volatile("ldmatrix.sync.aligned.m8n8.x4.shared.b16 {%0,%1,%2,%3}, [%4];"
                 : "=r"(r[0]), "=r"(r[1]), "=r"(r[2]), "=r"(r[3]) : "r"(addr));
}
__device__ __forceinline__ void mma16816(float* d, const uint32_t* a, const uint32_t* b) {
    asm volatile(
        "mma.sync.aligned.m16n8k16.row.col.f32.f16.f16.f32 "
        "{%0,%1,%2,%3}, {%4,%5,%6,%7}, {%8,%9}, {%0,%1,%2,%3};"
        : "+f"(d[0]), "+f"(d[1]), "+f"(d[2]), "+f"(d[3])
        : "r"(a[0]), "r"(a[1]), "r"(a[2]), "r"(a[3]), "r"(b[0]), "r"(b[1]));
}

// ---------------- prep ----------------
__global__ __launch_bounds__(256) void k_convert_rowinv(const float* __restrict__ A) {
    const int row = blockIdx.x;
    const int tid = threadIdx.x;
    const float4* p = (const float4*)(A + (size_t)row * DIM);
    float sum = 0.f;
    #pragma unroll
    for (int i = 0; i < 2; ++i) {
        int idx = tid + i * 256;
        float4 v = p[idx];
        float f[4] = {v.x, v.y, v.z, v.w};
        sum = fmaf(v.x, v.x, sum); sum = fmaf(v.y, v.y, sum);
        sum = fmaf(v.z, v.z, sum); sum = fmaf(v.w, v.w, sum);
        __half h[4], l[4];
        #pragma unroll
        for (int j = 0; j < 4; j++) {
            h[j] = __float2half(f[j]);
            l[j] = __float2half(f[j] - __half2float(h[j]));
        }
        size_t o = (size_t)row * 512 + idx;
        ((ushort4*)g_ahi)[o] = make_ushort4(__half_as_ushort(h[0]), __half_as_ushort(h[1]),
                                            __half_as_ushort(h[2]), __half_as_ushort(h[3]));
        ((ushort4*)g_alo)[o] = make_ushort4(__half_as_ushort(l[0]), __half_as_ushort(l[1]),
                                            __half_as_ushort(l[2]), __half_as_ushort(l[3]));
    }
    __shared__ float red[8];
    #pragma unroll
    for (int o = 16; o > 0; o >>= 1) sum += __shfl_xor_sync(0xffffffffu, sum, o);
    if ((tid & 31) == 0) red[tid >> 5] = sum;
    __syncthreads();
    if (tid == 0) {
        float s = 0.f;
        #pragma unroll
        for (int w = 0; w < 8; w++) s += red[w];
        g_inv[row] = (float)(1.0 / sqrt((double)s + 1.0));
    }
}

// also zeroes g_best (grid 1024 x 256 covers 16384 entries 16x over; use first 64 blocks)
__global__ void k_prep_centers(const float* __restrict__ C) {
    int k = blockIdx.x;
    int tid = threadIdx.x;
    {   // fused g_best init
        int gi = k * 256 + tid;
        if (gi < NROWS) g_best[gi] = 0ull;
    }
    if (k >= KC) {
        for (int i = tid; i < DIM; i += 256) {
            g_chi[(size_t)k * DIM + i] = __float2half(0.f);
            g_clo[(size_t)k * DIM + i] = __float2half(0.f);
        }
        if (tid == 0) { g_halfc[k] = 1e30f; g_clast[k] = 0.f; }
        return;
    }
    const float* row = C + (size_t)k * DSTR;
    double sum = 0.0;
    for (int i = tid; i < DSTR; i += 256) {
        float v = row[i];
        sum += (double)v * (double)v;
        if (i < DIM) {
            __half h = __float2half(v);
            g_chi[(size_t)k * DIM + i] = h;
            g_clo[(size_t)k * DIM + i] = __float2half(v - __half2float(h));
        }
    }
    __shared__ double red[8];
    #pragma unroll
    for (int o = 16; o > 0; o >>= 1) sum += __shfl_xor_sync(0xffffffffu, sum, o);
    if ((tid & 31) == 0) red[tid >> 5] = sum;
    __syncthreads();
    if (tid == 0) {
        double s = 0.0;
        #pragma unroll
        for (int w = 0; w < 8; w++) s += red[w];
        g_halfc[k] = (float)(0.5 * s);
        g_clast[k] = row[DIM];
    }
}

// ---------------- HMMA fp16-split GEMM + fused argmax ----------------
// R15 structure: 128 thr, 4 warps 2x2, warp tile 64x64, fused 3-product/k-step.
__global__ __launch_bounds__(128) void k_gemm_mma() {
    extern __shared__ char smem[];
    const uint32_t sb = smem_u32(smem);
    const int tid = threadIdx.x;
    const int wid = tid >> 5, lane = tid & 31;
    const int gid = lane >> 2, tig = lane & 3;
    const int n0 = blockIdx.x * 128;
    const int m0 = blockIdx.y * 128;
    const int wm = wid >> 1;       // 0..1, 64 m-rows
    const int wn = wid & 1;        // 0..1, 64 n-cols

    float acc[4][8][4];
    #pragma unroll
    for (int a = 0; a < 4; a++)
        #pragma unroll
        for (int b = 0; b < 8; b++)
            #pragma unroll
            for (int c = 0; c < 4; c++) acc[a][b][c] = 0.f;

    const int rc = tid >> 2;              // 0..31
    const int cc = tid & 3;               // 16B chunk in 64B row slab

    const uint32_t aoff = (uint32_t)((wm * 64 + (lane & 15)) * 80 + (lane >> 4) * 16);
    const uint32_t boff = (uint32_t)((wn * 64 + (lane & 7) + ((lane >> 4) << 3)) * 80
                                     + ((lane >> 3) & 1) * 16);

    // stage layout: [ah | al | bh | bl], each TILE_B
    #define LOAD_STAGE(s, st) do {                                              \
        int k0_ = (s) << 5;                                                     \
        uint32_t sa_ = sb + (st) * STAGE_BYTES;                                 \
        _Pragma("unroll")                                                       \
        for (int rb_ = 0; rb_ < 4; rb_++) {                                     \
            int r_ = rc + rb_ * 32;                                             \
            size_t ao_ = (size_t)(m0 + r_) * DIM + k0_ + cc * 8;                \
            size_t bo_ = (size_t)(n0 + r_) * DIM + k0_ + cc * 8;                \
            uint32_t so_ = r_ * 80 + cc * 16;                                   \
            cp16(sa_ + 0 * TILE_B + so_, g_ahi + ao_);                          \
            cp16(sa_ + 1 * TILE_B + so_, g_alo + ao_);                          \
            cp16(sa_ + 2 * TILE_B + so_, g_chi + bo_);                          \
            cp16(sa_ + 3 * TILE_B + so_, g_clo + bo_);                          \
        }                                                                       \
    } while (0)

    LOAD_STAGE(0, 0); CP_COMMIT();

    for (int s = 0; s < NSTEPS; ++s) {
        CP_WAIT(0);
        __syncthreads();
        if (s + 1 < NSTEPS) { LOAD_STAGE(s + 1, (s + 1) & 1); CP_COMMIT(); }

        const uint32_t st = sb + (s & 1) * STAGE_BYTES;
        #pragma unroll
        for (int kk = 0; kk < 2; ++kk) {
            uint32_t af_h[4][4], af_l[4][4];
            #pragma unroll
            for (int mf = 0; mf < 4; ++mf) {
                ldmx4(af_h[mf], st + 0 * TILE_B + aoff + mf * 1280 + kk * 32);
                ldmx4(af_l[mf], st + 1 * TILE_B + aoff + mf * 1280 + kk * 32);
            }
            uint32_t bf_h[8][2], bf_l[8][2];
            #pragma unroll
            for (int np = 0; np < 4; ++np) {
                uint32_t r[4];
                ldmx4(r, st + 2 * TILE_B + boff + np * 1280 + kk * 32);
                bf_h[2 * np][0] = r[0]; bf_h[2 * np][1] = r[1];
                bf_h[2 * np + 1][0] = r[2]; bf_h[2 * np + 1][1] = r[3];
                ldmx4(r, st + 3 * TILE_B + boff + np * 1280 + kk * 32);
                bf_l[2 * np][0] = r[0]; bf_l[2 * np][1] = r[1];
                bf_l[2 * np + 1][0] = r[2]; bf_l[2 * np + 1][1] = r[3];
            }
            #pragma unroll
            for (int mf = 0; mf < 4; ++mf)
                #pragma unroll
                for (int nf = 0; nf < 8; ++nf)
                    mma16816(acc[mf][nf], af_h[mf], bf_h[nf]);
            #pragma unroll
            for (int mf = 0; mf < 4; ++mf)
                #pragma unroll
                for (int nf = 0; nf < 8; ++nf)
                    mma16816(acc[mf][nf], af_h[mf], bf_l[nf]);
            #pragma unroll
            for (int mf = 0; mf < 4; ++mf)
                #pragma unroll
                for (int nf = 0; nf < 8; ++nf)
                    mma16816(acc[mf][nf], af_l[mf], bf_h[nf]);
        }
    }

    // -------- fused epilogue --------
    float cl[16], hc[16];
    #pragma unroll
    for (int nf = 0; nf < 8; ++nf)
        #pragma unroll
        for (int j = 0; j < 2; ++j) {
            int n = n0 + wn * 64 + nf * 8 + 2 * tig + j;
            cl[nf * 2 + j] = g_clast[n];
            hc[nf * 2 + j] = g_halfc[n];
        }

    #pragma unroll
    for (int mf = 0; mf < 4; ++mf)
        #pragma unroll
        for (int h = 0; h < 2; ++h) {
            int m = m0 + wm * 64 + mf * 16 + gid + 8 * h;
            float invm = g_inv[m];
            float bs = -FLT_MAX;
            int bn = 0x7FFFFFFF;
            #pragma unroll
            for (int nf = 0; nf < 8; ++nf)
                #pragma unroll
                for (int j = 0; j < 2; ++j) {
                    float s = fmaf(acc[mf][nf][2 * h + j] + cl[nf * 2 + j], invm,
                                   -hc[nf * 2 + j]);
                    int n = n0 + wn * 64 + nf * 8 + 2 * tig + j;
                    if (s > bs) { bs = s; bn = n; }
                }
            #pragma unroll
            for (int o = 1; o <= 2; o <<= 1) {
                float so = __shfl_xor_sync(0xffffffffu, bs, o);
                int   no = __shfl_xor_sync(0xffffffffu, bn, o);
                if (so > bs || (so == bs && no < bn)) { bs = so; bn = no; }
            }
            if (tig == 0) {
                unsigned sbits = __float_as_uint(bs);
                sbits = (sbits & 0x80000000u) ? ~sbits : (sbits | 0x80000000u);
                unsigned long long packed = ((unsigned long long)sbits << 32)
                    | (unsigned long long)(0xFFFFFFFFu - (unsigned)bn);
                atomicMax(&g_best[m], packed);
            }
        }
}

__global__ void k_decode(float* __restrict__ out) {
    int i = blockIdx.x * blockDim.x + threadIdx.x;
    if (i < NROWS)
        out[i] = (float)(0xFFFFFFFFu - (unsigned)(g_best[i] & 0xFFFFFFFFull));
}

extern "C" void kernel_launch(void* const* d_in, const int* in_sizes, int n_in,
                              void* d_out, int out_size) {
    (void)in_sizes; (void)n_in; (void)out_size;
    const float* feats = (const float*)d_in[0];
    const float* initc = (const float*)d_in[1];
    float* out = (float*)d_out;

    cudaFuncSetAttribute(k_gemm_mma, cudaFuncAttributeMaxDynamicSharedMemorySize, SM_TOTAL);

    k_prep_centers<<<NPAD, 256>>>(initc);     // also zeroes g_best
    k_convert_rowinv<<<NROWS, 256>>>(feats);

    dim3 grid(NPAD / 128, NROWS / 128);   // (8, 128) = 1024 CTAs
    k_gemm_mma<<<grid, 128, SM_TOTAL>>>();

    k_decode<<<(NROWS + 255) / 256, 256>>>(out);
}